// round 13
// baseline (speedup 1.0000x reference)
#include <cuda_runtime.h>
#include <cstdint>

#define T_LEN   1000000
#define HIDDEN  75
#define NS      16
#define BS      160                 // steps per ring block
#define NBLK    (T_LEN / BS)        // 6250
#define RB      4                   // ring slots
#define SLOT_F  (BS * 16)           // floats per slot (2560)
#define SLOT_BYTES (SLOT_F * 4)     // 10240

// g_np: per double-step records of 32 floats (negated log-priors, permuted):
//  lane0: [np[t][0..3]] [np[t][8..11]] [np[t+1][0],[1],[8],[9]] [np[t+1][4],[5],[12],[13]]
//  lane1: [np[t][5],[4],[7],[6]] [np[t][13],[12],[15],[14]]
//         [np[t+1][10],[11],[2],[3]] [np[t+1][14],[15],[6],[7]]
// g_ckpt: per block, lane0 stores (p0,p1,p2,p3), lane1 stores (p5,p4,p7,p6).
__device__ float g_np[T_LEN * 16];     // 64 MB
__device__ float g_ckpt[NBLK * 8];     // 200 KB

__device__ __forceinline__ int ld_acq(const int* p) {
    int v;
    asm volatile("ld.acquire.cta.b32 %0, [%1];" : "=r"(v) : "l"(p) : "memory");
    return v;
}
__device__ __forceinline__ void st_rel(int* p, int v) {
    asm volatile("st.release.cta.b32 [%0], %1;" :: "l"(p), "r"(v) : "memory");
}
__device__ __forceinline__ unsigned smem_u32(const void* p) {
    return (unsigned)__cvta_generic_to_shared(p);
}
// Raw butterfly shuffle: single SASS SHFL, warp convergent.
__device__ __forceinline__ float shfl_bfly_raw(float v) {
    float r;
    asm volatile("shfl.sync.bfly.b32 %0, %1, 1, 0x1f, 0xffffffff;" : "=f"(r) : "f"(v));
    return r;
}

// ================= K1: priors (unchanged from R12) =================
__global__ void k_priors(const float* __restrict__ rx,
                         const float* __restrict__ W1,
                         const float* __restrict__ b1,
                         const float* __restrict__ W2,
                         const float* __restrict__ b2,
                         int T) {
    __shared__ float sW1[HIDDEN], sb1[HIDDEN], sW2[HIDDEN * NS], sb2[NS];
    for (int i = threadIdx.x; i < HIDDEN; i += blockDim.x) { sW1[i] = W1[i]; sb1[i] = b1[i]; }
    for (int i = threadIdx.x; i < HIDDEN * NS; i += blockDim.x) sW2[i] = W2[i];
    if (threadIdx.x < NS) sb2[threadIdx.x] = b2[threadIdx.x];
    __syncthreads();

    int t = blockIdx.x * blockDim.x + threadIdx.x;
    if (t >= T) return;

    float x = rx[t];
    float acc[NS];
#pragma unroll
    for (int i = 0; i < NS; i++) acc[i] = 0.0f;

    for (int j = 0; j < HIDDEN; j++) {
        float h = __fadd_rn(__fmul_rn(x, sW1[j]), sb1[j]);
        h = fmaxf(h, 0.0f);
#pragma unroll
        for (int i = 0; i < NS; i++) acc[i] = fmaf(h, sW2[j * NS + i], acc[i]);
    }
#pragma unroll
    for (int i = 0; i < NS; i++) acc[i] = __fadd_rn(acc[i], sb2[i]);

    float m = acc[0];
#pragma unroll
    for (int i = 1; i < NS; i++) m = fmaxf(m, acc[i]);

    float sh[NS];
    float s = 0.0f;
#pragma unroll
    for (int i = 0; i < NS; i++) {
        sh[i] = __fadd_rn(acc[i], -m);
        s = __fadd_rn(s, expf(sh[i]));
    }
    float L = logf(s);

    float np[NS];
#pragma unroll
    for (int i = 0; i < NS; i++) np[i] = __fadd_rn(L, -sh[i]);   // negated prior

    float4* rec = (float4*)(g_np + (size_t)(t >> 1) * 32);
    if ((t & 1) == 0) {
        rec[0] = make_float4(np[0],  np[1],  np[2],  np[3]);
        rec[1] = make_float4(np[8],  np[9],  np[10], np[11]);
        rec[4] = make_float4(np[5],  np[4],  np[7],  np[6]);
        rec[5] = make_float4(np[13], np[12], np[15], np[14]);
    } else {
        rec[2] = make_float4(np[0],  np[1],  np[8],  np[9]);
        rec[3] = make_float4(np[4],  np[5],  np[12], np[13]);
        rec[6] = make_float4(np[10], np[11], np[2],  np[3]);
        rec[7] = make_float4(np[14], np[15], np[6],  np[7]);
    }
}

// ================= K2: 2-lane exact scan, TMA-fed ring =================
// Warp 0: scan (R12 arithmetic, double-buffered LDS).
// Thread 32: TMA producer (cp.async.bulk + mbarrier complete_tx).
__global__ void __launch_bounds__(64, 1) k_scan() {
    __shared__ __align__(128) float ring[RB * SLOT_F];       // 40 KB
    __shared__ __align__(8) unsigned long long mbar[RB];
    __shared__ int consumed;

    const int tid  = threadIdx.x;
    const int lane = tid & 31;
    const int wid  = tid >> 5;

    if (tid == 0) consumed = 0;
    if (tid == 32) {
#pragma unroll
        for (int s = 0; s < RB; s++) {
            unsigned a = smem_u32(&mbar[s]);
            asm volatile("mbarrier.init.shared.b64 [%0], 1;" :: "r"(a) : "memory");
        }
    }
    __syncthreads();

    if (wid == 0) {
        const int L = lane & 1;
        float u0 = 0.f, u1 = 0.f, u2 = 0.f, u3 = 0.f;
        for (int b = 0; b < NBLK; b++) {
            if (lane < 2) {
                *(float4*)(g_ckpt + (size_t)b * 8 + L * 4) = make_float4(u0, u1, u2, u3);
            }
            // wait for slot fill: parity = (b / RB) & 1
            {
                unsigned a = smem_u32(&mbar[b & (RB - 1)]);
                unsigned par = (unsigned)((b >> 2) & 1);
                asm volatile(
                    "{\n\t"
                    ".reg .pred P;\n\t"
                    "WL%=:\n\t"
                    "mbarrier.try_wait.parity.acquire.cta.shared::cta.b64 P, [%0], %1, 0x989680;\n\t"
                    "@!P bra WL%=;\n\t"
                    "}"
                    :: "r"(a), "r"(par) : "memory");
            }
            const float4* base = (const float4*)(ring + (b & (RB - 1)) * SLOT_F) + L * 4;
            float4 c0 = base[0], c1 = base[1], c2 = base[2], c3 = base[3];
#pragma unroll 2
            for (int r = 0; r < BS / 2; r++) {
                const int rn = (r + 1 < BS / 2) ? (r + 1) : r;
                float4 n0 = base[rn * 8 + 0];
                float4 n1 = base[rn * 8 + 1];
                float4 n2 = base[rn * 8 + 2];
                float4 n3 = base[rn * 8 + 3];
                // stage1 (step t)
                float A = fminf(__fadd_rn(u0, c0.x), __fadd_rn(u1, c0.y));
                float B = fminf(__fadd_rn(u2, c0.z), __fadd_rn(u3, c0.w));
                float C = fminf(__fadd_rn(u0, c1.x), __fadd_rn(u1, c1.y));
                float D = fminf(__fadd_rn(u2, c1.z), __fadd_rn(u3, c1.w));
                // stage2 (step t+1)
                float g0 = fminf(__fadd_rn(A, c2.x), __fadd_rn(B, c2.y));
                float g1 = fminf(__fadd_rn(A, c2.z), __fadd_rn(B, c2.w));
                float g2 = fminf(__fadd_rn(C, c3.x), __fadd_rn(D, c3.y));
                float g3 = fminf(__fadd_rn(C, c3.z), __fadd_rn(D, c3.w));
                // exchange
                u1 = shfl_bfly_raw(g1);
                u3 = shfl_bfly_raw(g3);
                u0 = g0; u2 = g2;
                c0 = n0; c1 = n1; c2 = n2; c3 = n3;
            }
            if (lane == 0) st_rel(&consumed, b + 1);
        }
    } else if (tid == 32) {
        // TMA producer
        for (int b = 0; b < NBLK; b++) {
            while (b >= RB && ld_acq(&consumed) < b - RB + 1) __nanosleep(64);
            unsigned a   = smem_u32(&mbar[b & (RB - 1)]);
            unsigned dst = smem_u32(ring + (b & (RB - 1)) * SLOT_F);
            const float* src = g_np + (size_t)b * SLOT_F;
            asm volatile("mbarrier.arrive.expect_tx.shared.b64 _, [%0], %1;"
                         :: "r"(a), "r"((unsigned)SLOT_BYTES) : "memory");
            asm volatile("cp.async.bulk.shared::cta.global.mbarrier::complete_tx::bytes "
                         "[%0], [%1], %2, [%3];"
                         :: "r"(dst), "l"(src), "r"((unsigned)SLOT_BYTES), "r"(a) : "memory");
        }
    }
}

// ================= K3: parallel det/conf emission (unchanged from R12) =================
__global__ void k_emit(float* __restrict__ out_det, float* __restrict__ out_conf) {
    int c = blockIdx.x * blockDim.x + threadIdx.x;
    if (c >= NBLK) return;

    float p[8];
    {
        float4 a = *(const float4*)(g_ckpt + (size_t)c * 8);
        float4 b = *(const float4*)(g_ckpt + (size_t)c * 8 + 4);
        p[0] = a.x; p[1] = a.y; p[2] = a.z; p[3] = a.w;
        p[4] = b.y; p[5] = b.x; p[6] = b.w; p[7] = b.z;
    }

    const float4* rec = (const float4*)(g_np + (size_t)c * SLOT_F);
    const int tbase = c * BS;

    for (int r = 0; r < BS / 2; r++) {
        float4 v0 = rec[r * 8 + 0], v1 = rec[r * 8 + 1];
        float4 v2 = rec[r * 8 + 2], v3 = rec[r * 8 + 3];
        float4 v4 = rec[r * 8 + 4], v5 = rec[r * 8 + 5];
        float4 v6 = rec[r * 8 + 6], v7 = rec[r * 8 + 7];

        float nvA[16] = { v0.x, v0.y, v0.z, v0.w,
                          v4.y, v4.x, v4.w, v4.z,
                          v1.x, v1.y, v1.z, v1.w,
                          v5.y, v5.x, v5.w, v5.z };
        float nvB[16] = { v2.x, v2.y, v6.z, v6.w,
                          v3.x, v3.y, v7.z, v7.w,
                          v2.z, v2.w, v6.x, v6.y,
                          v3.z, v3.w, v7.x, v7.y };

#pragma unroll
        for (int half = 0; half < 2; half++) {
            const float* nv = half ? nvB : nvA;
            float best = p[0];
            int idx = 0;
#pragma unroll
            for (int j = 1; j < 8; j++) {
                if (p[j] < best) { best = p[j]; idx = j; }
            }
            float e[8];
#pragma unroll
            for (int j = 0; j < 8; j++) e[j] = expf(__fadd_rn(best, -p[j]));
            float S = e[0];
#pragma unroll
            for (int j = 1; j < 8; j++) S = __fadd_rn(S, e[j]);
#pragma unroll
            for (int j = 0; j < 8; j++) S = __fadd_rn(S, e[j]);
            float conf = __fdiv_rn(1.0f, S);

            int k = r * 2 + half;
            out_det[tbase + k]  = (float)(idx & 1);
            out_conf[tbase + k] = __fmul_rn(2.0f, conf);

            float newp[8];
#pragma unroll
            for (int i = 0; i < 8; i++) {
                int a2 = (2 * i) & 7;
                newp[i] = fminf(__fadd_rn(p[a2],     nv[2 * i]),
                                __fadd_rn(p[a2 + 1], nv[2 * i + 1]));
            }
#pragma unroll
            for (int i = 0; i < 8; i++) p[i] = newp[i];
        }
    }
}

// ================= launch =================
extern "C" void kernel_launch(void* const* d_in, const int* in_sizes, int n_in,
                              void* d_out, int out_size) {
    const float* rx = (const float*)d_in[0];
    const float* W1 = (const float*)d_in[1];
    const float* b1 = (const float*)d_in[2];
    const float* W2 = (const float*)d_in[3];
    const float* b2 = (const float*)d_in[4];
    float* out = (float*)d_out;

    int T = in_sizes[0];
    if (T > T_LEN) T = T_LEN;

    k_priors<<<(T + 255) / 256, 256>>>(rx, W1, b1, W2, b2, T);
    k_scan<<<1, 64>>>();
    k_emit<<<(NBLK + 127) / 128, 128>>>(out, out + T);
}

// round 15
// speedup vs baseline: 1.1936x; 1.1936x over previous
#include <cuda_runtime.h>
#include <cstdint>

#define T_LEN   1000000
#define HIDDEN  75
#define NS      16
#define BS      160                // steps per checkpoint block
#define NBLK    (T_LEN / BS)       // 6250
#define RB      4                  // ring blocks (smem), 40KB ring

// g_np: per double-step records of 32 floats (negated log-priors, permuted):
//  lane0: [np[t][0..3]] [np[t][8..11]] [np[t+1][0],[1],[8],[9]] [np[t+1][4],[5],[12],[13]]
//  lane1: [np[t][5],[4],[7],[6]] [np[t][13],[12],[15],[14]]
//         [np[t+1][10],[11],[2],[3]] [np[t+1][14],[15],[6],[7]]
// g_ckpt: per block, lane0 stores (p0,p1,p2,p3), lane1 stores (p5,p4,p7,p6).
__device__ float g_np[T_LEN * 16];     // 64 MB
__device__ float g_ckpt[NBLK * 8];     // 200 KB

__device__ __forceinline__ int ld_acq(const int* p) {
    int v;
    asm volatile("ld.acquire.cta.b32 %0, [%1];" : "=r"(v) : "l"(p) : "memory");
    return v;
}
__device__ __forceinline__ void st_rel(int* p, int v) {
    asm volatile("st.release.cta.b32 [%0], %1;" :: "l"(p), "r"(v) : "memory");
}
// Raw butterfly shuffle: single SASS SHFL. NON-volatile: pure value op, lets
// ptxas/SASS scheduler hoist it and overlap its 26-cycle latency with
// independent FADD/FMNMX work. Float constraints ('f') as in R12.
__device__ __forceinline__ float shfl_bfly_raw(float v) {
    float r;
    asm("shfl.sync.bfly.b32 %0, %1, 1, 0x1f, 0xffffffff;" : "=f"(r) : "f"(v));
    return r;
}

// ================= K1: priors (unchanged from R12) =================
__global__ void k_priors(const float* __restrict__ rx,
                         const float* __restrict__ W1,
                         const float* __restrict__ b1,
                         const float* __restrict__ W2,
                         const float* __restrict__ b2,
                         int T) {
    __shared__ float sW1[HIDDEN], sb1[HIDDEN], sW2[HIDDEN * NS], sb2[NS];
    for (int i = threadIdx.x; i < HIDDEN; i += blockDim.x) { sW1[i] = W1[i]; sb1[i] = b1[i]; }
    for (int i = threadIdx.x; i < HIDDEN * NS; i += blockDim.x) sW2[i] = W2[i];
    if (threadIdx.x < NS) sb2[threadIdx.x] = b2[threadIdx.x];
    __syncthreads();

    int t = blockIdx.x * blockDim.x + threadIdx.x;
    if (t >= T) return;

    float x = rx[t];
    float acc[NS];
#pragma unroll
    for (int i = 0; i < NS; i++) acc[i] = 0.0f;

    for (int j = 0; j < HIDDEN; j++) {
        float h = __fadd_rn(__fmul_rn(x, sW1[j]), sb1[j]);
        h = fmaxf(h, 0.0f);
#pragma unroll
        for (int i = 0; i < NS; i++) acc[i] = fmaf(h, sW2[j * NS + i], acc[i]);
    }
#pragma unroll
    for (int i = 0; i < NS; i++) acc[i] = __fadd_rn(acc[i], sb2[i]);

    float m = acc[0];
#pragma unroll
    for (int i = 1; i < NS; i++) m = fmaxf(m, acc[i]);

    float sh[NS];
    float s = 0.0f;
#pragma unroll
    for (int i = 0; i < NS; i++) {
        sh[i] = __fadd_rn(acc[i], -m);
        s = __fadd_rn(s, expf(sh[i]));
    }
    float L = logf(s);

    float np[NS];
#pragma unroll
    for (int i = 0; i < NS; i++) np[i] = __fadd_rn(L, -sh[i]);   // negated prior

    float4* rec = (float4*)(g_np + (size_t)(t >> 1) * 32);
    if ((t & 1) == 0) {
        rec[0] = make_float4(np[0],  np[1],  np[2],  np[3]);
        rec[1] = make_float4(np[8],  np[9],  np[10], np[11]);
        rec[4] = make_float4(np[5],  np[4],  np[7],  np[6]);
        rec[5] = make_float4(np[13], np[12], np[15], np[14]);
    } else {
        rec[2] = make_float4(np[0],  np[1],  np[8],  np[9]);
        rec[3] = make_float4(np[4],  np[5],  np[12], np[13]);
        rec[6] = make_float4(np[10], np[11], np[2],  np[3]);
        rec[7] = make_float4(np[14], np[15], np[6],  np[7]);
    }
}

// ================= K2: exact sequential scan, 2-lane split =================
// Warp 0: even lanes role 0 (p0,p1,p2,p3), odd lanes role 1 (p5,p4,p7,p6).
// Per double-step the exchanged values (g1,g3) are computed FIRST and their
// shuffles issued early, so g0/g2 and next-iteration loads overlap SHFL latency.
// Warps 1-3: stage priors global->smem ring.
__global__ void __launch_bounds__(128, 1) k_scan() {
    __shared__ __align__(16) float ring[RB * BS * 16];   // 40 KB
    __shared__ int flag[RB];
    __shared__ int consumed;

    const int tid  = threadIdx.x;
    const int wid  = tid >> 5;
    const int lane = tid & 31;

    if (tid < RB) flag[tid] = 0;
    if (tid == 0) consumed = 0;
    __syncthreads();

    if (wid == 0) {
        const int L = lane & 1;
        float u0 = 0.f, u1 = 0.f, u2 = 0.f, u3 = 0.f;
        for (int b = 0; b < NBLK; b++) {
            if (lane < 2) {
                *(float4*)(g_ckpt + (size_t)b * 8 + L * 4) = make_float4(u0, u1, u2, u3);
            }
            while (ld_acq(&flag[b & (RB - 1)]) != b + 1) { }
            const float4* base = (const float4*)(&ring[(b & (RB - 1)) * (BS * 16)] + L * 16);
#pragma unroll 8
            for (int r = 0; r < BS / 2; r++) {
                float4 q0 = base[r * 8 + 0];
                float4 q1 = base[r * 8 + 1];
                float4 q2 = base[r * 8 + 2];
                float4 q3 = base[r * 8 + 3];
                // stage1 first half (feeds g1 — the exchanged value)
                float A = fminf(__fadd_rn(u0, q0.x), __fadd_rn(u1, q0.y));
                float B = fminf(__fadd_rn(u2, q0.z), __fadd_rn(u3, q0.w));
                // exchanged value #1, shuffle issued as early as possible
                float g1 = fminf(__fadd_rn(A, q2.z), __fadd_rn(B, q2.w));
                float u1n = shfl_bfly_raw(g1);
                // stage1 second half (feeds g3)
                float C = fminf(__fadd_rn(u0, q1.x), __fadd_rn(u1, q1.y));
                float D = fminf(__fadd_rn(u2, q1.z), __fadd_rn(u3, q1.w));
                // exchanged value #2
                float g3 = fminf(__fadd_rn(C, q3.z), __fadd_rn(D, q3.w));
                float u3n = shfl_bfly_raw(g3);
                // retained values — computed while shuffles are in flight
                float g0 = fminf(__fadd_rn(A, q2.x), __fadd_rn(B, q2.y));
                float g2 = fminf(__fadd_rn(C, q3.x), __fadd_rn(D, q3.y));
                u0 = g0; u2 = g2;
                u1 = u1n; u3 = u3n;
            }
            if (lane == 0) st_rel(&consumed, b + 1);
        }
    } else {
        // copier warps: wid 1..3 handle blocks b with b % 3 == wid-1
        for (int b = wid - 1; b < NBLK; b += 3) {
            while (b >= RB && ld_acq(&consumed) < b - RB + 1) __nanosleep(100);
            const float4* src = (const float4*)(g_np + (size_t)b * (BS * 16));
            float4* dst = (float4*)&ring[(b & (RB - 1)) * (BS * 16)];
#pragma unroll
            for (int r = 0; r < (BS * 16 / 4) / 32; r++)   // 20 float4 per lane
                dst[r * 32 + lane] = src[r * 32 + lane];
            __syncwarp();
            if (lane == 0) st_rel(&flag[b & (RB - 1)], b + 1);
        }
    }
}

// ================= K3: parallel det/conf emission (unchanged from R12) =================
__global__ void k_emit(float* __restrict__ out_det, float* __restrict__ out_conf) {
    int c = blockIdx.x * blockDim.x + threadIdx.x;
    if (c >= NBLK) return;

    float p[8];
    {
        float4 a = *(const float4*)(g_ckpt + (size_t)c * 8);
        float4 b = *(const float4*)(g_ckpt + (size_t)c * 8 + 4);
        p[0] = a.x; p[1] = a.y; p[2] = a.z; p[3] = a.w;
        p[4] = b.y; p[5] = b.x; p[6] = b.w; p[7] = b.z;
    }

    const float4* rec = (const float4*)(g_np + (size_t)c * (BS * 16));
    const int tbase = c * BS;

    for (int r = 0; r < BS / 2; r++) {
        float4 v0 = rec[r * 8 + 0], v1 = rec[r * 8 + 1];
        float4 v2 = rec[r * 8 + 2], v3 = rec[r * 8 + 3];
        float4 v4 = rec[r * 8 + 4], v5 = rec[r * 8 + 5];
        float4 v6 = rec[r * 8 + 6], v7 = rec[r * 8 + 7];

        float nvA[16] = { v0.x, v0.y, v0.z, v0.w,
                          v4.y, v4.x, v4.w, v4.z,
                          v1.x, v1.y, v1.z, v1.w,
                          v5.y, v5.x, v5.w, v5.z };
        float nvB[16] = { v2.x, v2.y, v6.z, v6.w,
                          v3.x, v3.y, v7.z, v7.w,
                          v2.z, v2.w, v6.x, v6.y,
                          v3.z, v3.w, v7.x, v7.y };

#pragma unroll
        for (int half = 0; half < 2; half++) {
            const float* nv = half ? nvB : nvA;
            float best = p[0];
            int idx = 0;
#pragma unroll
            for (int j = 1; j < 8; j++) {
                if (p[j] < best) { best = p[j]; idx = j; }
            }
            float e[8];
#pragma unroll
            for (int j = 0; j < 8; j++) e[j] = expf(__fadd_rn(best, -p[j]));
            float S = e[0];
#pragma unroll
            for (int j = 1; j < 8; j++) S = __fadd_rn(S, e[j]);
#pragma unroll
            for (int j = 0; j < 8; j++) S = __fadd_rn(S, e[j]);
            float conf = __fdiv_rn(1.0f, S);

            int k = r * 2 + half;
            out_det[tbase + k]  = (float)(idx & 1);
            out_conf[tbase + k] = __fmul_rn(2.0f, conf);

            float newp[8];
#pragma unroll
            for (int i = 0; i < 8; i++) {
                int a2 = (2 * i) & 7;
                newp[i] = fminf(__fadd_rn(p[a2],     nv[2 * i]),
                                __fadd_rn(p[a2 + 1], nv[2 * i + 1]));
            }
#pragma unroll
            for (int i = 0; i < 8; i++) p[i] = newp[i];
        }
    }
}

// ================= launch =================
extern "C" void kernel_launch(void* const* d_in, const int* in_sizes, int n_in,
                              void* d_out, int out_size) {
    const float* rx = (const float*)d_in[0];
    const float* W1 = (const float*)d_in[1];
    const float* b1 = (const float*)d_in[2];
    const float* W2 = (const float*)d_in[3];
    const float* b2 = (const float*)d_in[4];
    float* out = (float*)d_out;

    int T = in_sizes[0];
    if (T > T_LEN) T = T_LEN;

    k_priors<<<(T + 255) / 256, 256>>>(rx, W1, b1, W2, b2, T);
    k_scan<<<1, 128>>>();
    k_emit<<<(NBLK + 127) / 128, 128>>>(out, out + T);
}